// round 1
// baseline (speedup 1.0000x reference)
#include <cuda_runtime.h>
#include <math.h>

#define B_   8
#define T_   1024
#define D_   640
#define H_   10
#define HD   64
#define MTOT (B_*T_)      // 8192
#define NEG_BIG (-4294967295.0f)   // -2^32+1

__device__ float g_Q[MTOT * D_];
__device__ float g_K[MTOT * D_];
__device__ float g_V[MTOT * D_];

// ---------------------------------------------------------------------------
// QKV projection: out = x @ W.   M=8192, N=640, K=640.
// 64x64 tile, BK=16, 256 threads, 4x4 register blocking.
// blockIdx.z selects (Wq->g_Q, Wk->g_K, Wv->g_V).
// ---------------------------------------------------------------------------
__global__ void __launch_bounds__(256) proj_kernel(
        const float* __restrict__ x,
        const float* __restrict__ Wq,
        const float* __restrict__ Wk,
        const float* __restrict__ Wv)
{
    const float* W;
    float* out;
    if (blockIdx.z == 0)      { W = Wq; out = g_Q; }
    else if (blockIdx.z == 1) { W = Wk; out = g_K; }
    else                      { W = Wv; out = g_V; }

    __shared__ float As[16][64];   // [k][m]
    __shared__ float Bs[16][64];   // [k][n]

    const int t  = threadIdx.x;
    const int tx = t & 15;
    const int ty = t >> 4;
    const int row0 = blockIdx.y * 64;
    const int col0 = blockIdx.x * 64;

    float acc[4][4] = {};

    for (int k0 = 0; k0 < D_; k0 += 16) {
        // A: 64 rows x 16 k  (transpose into [k][m])
        {
            int r  = t >> 2;
            int kk = (t & 3) << 2;
            float4 v = *(const float4*)(x + (size_t)(row0 + r) * D_ + k0 + kk);
            As[kk + 0][r] = v.x;
            As[kk + 1][r] = v.y;
            As[kk + 2][r] = v.z;
            As[kk + 3][r] = v.w;
        }
        // B: 16 k x 64 n
        {
            int kk = t >> 4;
            int c  = (t & 15) << 2;
            *(float4*)&Bs[kk][c] =
                *(const float4*)(W + (size_t)(k0 + kk) * D_ + col0 + c);
        }
        __syncthreads();

        #pragma unroll
        for (int kk = 0; kk < 16; kk++) {
            float a[4], bb[4];
            #pragma unroll
            for (int i = 0; i < 4; i++) a[i]  = As[kk][ty * 4 + i];
            #pragma unroll
            for (int j = 0; j < 4; j++) bb[j] = Bs[kk][tx * 4 + j];
            #pragma unroll
            for (int i = 0; i < 4; i++)
                #pragma unroll
                for (int j = 0; j < 4; j++)
                    acc[i][j] = fmaf(a[i], bb[j], acc[i][j]);
        }
        __syncthreads();
    }

    #pragma unroll
    for (int i = 0; i < 4; i++) {
        float4 v = make_float4(acc[i][0], acc[i][1], acc[i][2], acc[i][3]);
        *(float4*)(out + (size_t)(row0 + ty * 4 + i) * D_ + col0 + tx * 4) = v;
    }
}

// ---------------------------------------------------------------------------
// Flash-style attention.  One block = one (head, batch, 64-row q-tile).
// Online softmax over 64-key tiles.  Exact skip of fully-masked k-tiles
// (valid for q0 > 0: exp(s - 10000 - m) == 0 exactly in fp32).
// ---------------------------------------------------------------------------
#define ATTN_SMEM (4 * 64 * 64 * 4 + 5 * 64 * 4)

__global__ void __launch_bounds__(256) attn_kernel(
        const int* __restrict__ mask, float* __restrict__ out)
{
    const int q0 = blockIdx.x * 64;
    const int hb = blockIdx.y;        // 0..79
    const int b  = hb & 7;
    const int h  = hb >> 3;

    extern __shared__ float smem[];
    float (*Qs)[64]  = (float(*)[64])(smem);             // [qrow][dim]
    float (*Kst)[64] = (float(*)[64])(smem + 4096);      // [dim][kcol] (transposed)
    float (*Vs)[64]  = (float(*)[64])(smem + 8192);      // [krow][dim]
    float (*Ss)[64]  = (float(*)[64])(smem + 12288);     // scores, then probs
    float* m_sh  = smem + 16384;
    float* l_sh  = m_sh + 64;
    float* al_sh = l_sh + 64;
    float* qm_sh = al_sh + 64;
    float* km_sh = qm_sh + 64;

    const int t  = threadIdx.x;
    const int tx = t & 15;
    const int ty = t >> 4;
    const int rowA = ty * 4;
    const int colA = tx * 4;
    const float scale = 0.125f;   // 1/sqrt(64)

    // ---- load Q tile
    {
        size_t qbase = (size_t)(b * T_ + q0) * D_ + h * HD;
        #pragma unroll
        for (int e = t * 4; e < 4096; e += 1024) {
            int r = e >> 6, c = e & 63;
            *(float4*)&Qs[r][c] = *(const float4*)(g_Q + qbase + (size_t)r * D_ + c);
        }
    }
    if (t < 64) { m_sh[t] = -INFINITY; l_sh[t] = 0.0f; }
    __syncthreads();

    if (t < 64) {
        float s = 0.0f;
        #pragma unroll 8
        for (int c = 0; c < 64; c++) s += fabsf(Qs[t][c]);
        qm_sh[t] = (s != 0.0f) ? 1.0f : 0.0f;
    }

    float O[4][4] = {};

    const int nkt = (q0 == 0) ? (T_ / 64) : ((q0 >> 6) + 1);

    for (int kt = 0; kt < nkt; kt++) {
        const int k0 = kt * 64;
        __syncthreads();   // protect Kst/Vs/Ss from previous iteration readers

        // ---- load K (transposed) and V tiles
        {
            size_t kbase = (size_t)(b * T_ + k0) * D_ + h * HD;
            #pragma unroll
            for (int e = t * 4; e < 4096; e += 1024) {
                int r = e >> 6, c = e & 63;
                float4 kv = *(const float4*)(g_K + kbase + (size_t)r * D_ + c);
                Kst[c + 0][r] = kv.x;
                Kst[c + 1][r] = kv.y;
                Kst[c + 2][r] = kv.z;
                Kst[c + 3][r] = kv.w;
                *(float4*)&Vs[r][c] = *(const float4*)(g_V + kbase + (size_t)r * D_ + c);
            }
        }
        __syncthreads();

        // key padding mask for this tile
        if (t < 64) {
            float s = 0.0f;
            #pragma unroll 8
            for (int kk = 0; kk < 64; kk++) s += fabsf(Kst[kk][t]);
            km_sh[t] = (s != 0.0f) ? 1.0f : 0.0f;
        }
        __syncthreads();

        // ---- S = Q K^T * scale
        float s[4][4] = {};
        #pragma unroll 8
        for (int kk = 0; kk < 64; kk++) {
            float a[4], bb[4];
            #pragma unroll
            for (int i = 0; i < 4; i++) a[i]  = Qs[rowA + i][kk];
            #pragma unroll
            for (int j = 0; j < 4; j++) bb[j] = Kst[kk][colA + j];
            #pragma unroll
            for (int i = 0; i < 4; i++)
                #pragma unroll
                for (int j = 0; j < 4; j++)
                    s[i][j] = fmaf(a[i], bb[j], s[i][j]);
        }

        // ---- masks, stage scores to smem for row-max
        #pragma unroll
        for (int i = 0; i < 4; i++) {
            int qrow = q0 + rowA + i;
            #pragma unroll
            for (int j = 0; j < 4; j++) {
                int kcol = k0 + colA + j;
                float v = s[i][j] * scale;
                if (km_sh[colA + j] == 0.0f) v = NEG_BIG;
                if (qrow <= kcol) v += -10000.0f;
                s[i][j] = v;
                Ss[rowA + i][colA + j] = v;
            }
        }
        __syncthreads();

        // ---- per-row running max / alpha
        if (t < 64) {
            float tm = -INFINITY;
            #pragma unroll 8
            for (int c = 0; c < 64; c++) tm = fmaxf(tm, Ss[t][c]);
            float mold = m_sh[t];
            float mnew = fmaxf(mold, tm);
            m_sh[t]  = mnew;
            al_sh[t] = __expf(mold - mnew);   // 0 on first tile (mold = -inf)
        }
        __syncthreads();

        // ---- P = exp(S - m), rescale O
        float mrow[4], arow[4];
        #pragma unroll
        for (int i = 0; i < 4; i++) {
            mrow[i] = m_sh[rowA + i];
            arow[i] = al_sh[rowA + i];
        }
        #pragma unroll
        for (int i = 0; i < 4; i++)
            #pragma unroll
            for (int j = 0; j < 4; j++) {
                float p = __expf(s[i][j] - mrow[i]);
                Ss[rowA + i][colA + j] = p;
                O[i][j] *= arow[i];
            }
        __syncthreads();

        // ---- row-sum update (threads 0..63) runs alongside PV (all threads)
        if (t < 64) {
            float sum = 0.0f;
            #pragma unroll 8
            for (int c = 0; c < 64; c++) sum += Ss[t][c];
            l_sh[t] = l_sh[t] * al_sh[t] + sum;
        }

        // ---- O += P @ V
        #pragma unroll 8
        for (int kk = 0; kk < 64; kk++) {
            float p[4], vv[4];
            #pragma unroll
            for (int i = 0; i < 4; i++) p[i]  = Ss[rowA + i][kk];
            #pragma unroll
            for (int j = 0; j < 4; j++) vv[j] = Vs[kk][colA + j];
            #pragma unroll
            for (int i = 0; i < 4; i++)
                #pragma unroll
                for (int j = 0; j < 4; j++)
                    O[i][j] = fmaf(p[i], vv[j], O[i][j]);
        }
    }

    __syncthreads();   // final l_sh writes visible to all

    // ---- epilogue: normalize, query mask, final row mask, store
    #pragma unroll
    for (int i = 0; i < 4; i++) {
        int qrow = q0 + rowA + i;
        float inv = 1.0f / l_sh[rowA + i];
        float mm  = qm_sh[rowA + i] * (float)mask[b * T_ + qrow];
        float f   = inv * mm;
        float4 v  = make_float4(O[i][0] * f, O[i][1] * f, O[i][2] * f, O[i][3] * f);
        *(float4*)(out + (size_t)(b * T_ + qrow) * D_ + h * HD + colA) = v;
    }
}

// ---------------------------------------------------------------------------
extern "C" void kernel_launch(void* const* d_in, const int* in_sizes, int n_in,
                              void* d_out, int out_size)
{
    const float* x    = (const float*)d_in[0];
    const int*   mask = (const int*)d_in[1];
    const float* Wq   = (const float*)d_in[2];
    const float* Wk   = (const float*)d_in[3];
    const float* Wv   = (const float*)d_in[4];
    float* out = (float*)d_out;

    cudaFuncSetAttribute(attn_kernel,
                         cudaFuncAttributeMaxDynamicSharedMemorySize, ATTN_SMEM);

    dim3 gproj(D_ / 64, MTOT / 64, 3);
    proj_kernel<<<gproj, 256>>>(x, Wq, Wk, Wv);

    dim3 gattn(T_ / 64, H_ * B_);
    attn_kernel<<<gattn, 256, ATTN_SMEM>>>(mask, out);
}

// round 5
// speedup vs baseline: 1.4295x; 1.4295x over previous
#include <cuda_runtime.h>
#include <cuda_bf16.h>
#include <math.h>
#include <stdint.h>

#define B_   8
#define T_   1024
#define D_   640
#define H_   10
#define HD   64
#define MTOT (B_*T_)      // 8192
#define NEG_BIG (-4294967295.0f)   // -2^32+1

__device__ float g_Q[MTOT * D_];
__device__ float g_K[MTOT * D_];
__device__ float g_V[MTOT * D_];

// ===========================================================================
// Warp-level tensor-core helpers (baseline PTX, sm_80+, valid on sm_100)
// ===========================================================================
__device__ __forceinline__ uint32_t smem_u32(const void* p) {
    uint32_t a;
    asm("{ .reg .u64 t; cvta.to.shared.u64 t, %1; cvt.u32.u64 %0, t; }"
        : "=r"(a) : "l"(p));
    return a;
}

__device__ __forceinline__ void ldsm_x4(uint32_t* r, uint32_t addr) {
    asm volatile("ldmatrix.sync.aligned.m8n8.x4.shared.b16 {%0,%1,%2,%3}, [%4];"
        : "=r"(r[0]), "=r"(r[1]), "=r"(r[2]), "=r"(r[3]) : "r"(addr));
}
__device__ __forceinline__ void ldsm_x4_t(uint32_t* r, uint32_t addr) {
    asm volatile("ldmatrix.sync.aligned.m8n8.x4.trans.shared.b16 {%0,%1,%2,%3}, [%4];"
        : "=r"(r[0]), "=r"(r[1]), "=r"(r[2]), "=r"(r[3]) : "r"(addr));
}

__device__ __forceinline__ void mma16816(float* c, const uint32_t* a,
                                         uint32_t b0, uint32_t b1) {
    asm volatile(
        "mma.sync.aligned.m16n8k16.row.col.f32.bf16.bf16.f32 "
        "{%0,%1,%2,%3}, {%4,%5,%6,%7}, {%8,%9}, {%0,%1,%2,%3};"
        : "+f"(c[0]), "+f"(c[1]), "+f"(c[2]), "+f"(c[3])
        : "r"(a[0]), "r"(a[1]), "r"(a[2]), "r"(a[3]), "r"(b0), "r"(b1));
}

// split pair (a,b) into bf16 hi/lo, packed bf16x2
__device__ __forceinline__ void bf16_split2(float a, float b,
                                            uint32_t& hi, uint32_t& lo) {
    __nv_bfloat16 ah = __float2bfloat16(a);
    __nv_bfloat16 bh = __float2bfloat16(b);
    __nv_bfloat16 al = __float2bfloat16(a - __bfloat162float(ah));
    __nv_bfloat16 bl = __float2bfloat16(b - __bfloat162float(bh));
    hi = (uint32_t)*(uint16_t*)&ah | ((uint32_t)*(uint16_t*)&bh << 16);
    lo = (uint32_t)*(uint16_t*)&al | ((uint32_t)*(uint16_t*)&bl << 16);
}

// ===========================================================================
// Projection: C[8192,640] = x @ W via mma.sync bf16 (3-term hi/lo split).
// CTA tile M=128 x N=64, BK=64.  8 warps (4m x 2n), warp tile 32x32.
// A smem: [128][72] bf16 (hi+lo).   B smem: [64][72] bf16 (hi+lo), natural
// [k][n] layout (coalesced stores), ldmatrix.trans for fragments.
// ===========================================================================
#define LDA 72
#define LDB 72
#define PJ_AHI 0
#define PJ_ALO (128 * LDA * 2)                 // 18432
#define PJ_BHI (2 * 128 * LDA * 2)             // 36864
#define PJ_BLO (2 * 128 * LDA * 2 + 64 * LDB * 2)  // 46080
#define PJ_SMEM (2 * 128 * LDA * 2 + 2 * 64 * LDB * 2)  // 55296

__global__ void __launch_bounds__(256) proj_tc_kernel(
        const float* __restrict__ x,
        const float* __restrict__ Wq,
        const float* __restrict__ Wk,
        const float* __restrict__ Wv)
{
    const float* W;
    float* out;
    if (blockIdx.z == 0)      { W = Wq; out = g_Q; }
    else if (blockIdx.z == 1) { W = Wk; out = g_K; }
    else                      { W = Wv; out = g_V; }

    extern __shared__ char smem[];
    const uint32_t sb = smem_u32(smem);

    const int tid  = threadIdx.x;
    const int lane = tid & 31;
    const int wid  = tid >> 5;
    const int wm   = (wid & 3) * 32;   // warp m offset in CTA tile
    const int wn   = (wid >> 2) * 32;  // warp n offset

    const int row0 = blockIdx.y * 128;
    const int col0 = blockIdx.x * 64;

    float acc[2][4][4] = {};   // [mi][ni][frag]

    for (int c = 0; c < 10; c++) {
        const int k0 = c * 64;
        if (c > 0) __syncthreads();   // previous compute done before overwrite

        // ---- load A chunk: x[row0..+127][k0..+63] -> Ahi/Alo
        #pragma unroll
        for (int i = 0; i < 8; i++) {
            int lin = tid + i * 256;
            int r = lin >> 4, q = lin & 15;
            float4 v = *(const float4*)(x + (size_t)(row0 + r) * D_ + k0 + q * 4);
            uint2 hv, lv;
            bf16_split2(v.x, v.y, hv.x, lv.x);
            bf16_split2(v.z, v.w, hv.y, lv.y);
            uint32_t off = (uint32_t)(r * LDA + q * 4) * 2;
            *(uint2*)(smem + PJ_AHI + off) = hv;
            *(uint2*)(smem + PJ_ALO + off) = lv;
        }
        // ---- load B chunk: W[k0..+63][col0..+63] -> Bhi/Blo ([k][n] layout)
        #pragma unroll
        for (int i = 0; i < 4; i++) {
            int lin = tid + i * 256;
            int kk = lin >> 4, nq = lin & 15;
            float4 v = *(const float4*)(W + (size_t)(k0 + kk) * D_ + col0 + nq * 4);
            uint2 hv, lv;
            bf16_split2(v.x, v.y, hv.x, lv.x);
            bf16_split2(v.z, v.w, hv.y, lv.y);
            uint32_t off = (uint32_t)(kk * LDB + nq * 4) * 2;
            *(uint2*)(smem + PJ_BHI + off) = hv;
            *(uint2*)(smem + PJ_BLO + off) = lv;
        }
        __syncthreads();

        #pragma unroll
        for (int ks = 0; ks < 4; ks++) {
            const int k = ks * 16;

            // A fragments: mi = 0,1 (rows wm+mi*16 .. +15)
            uint32_t ah[2][4], al[2][4];
            #pragma unroll
            for (int mi = 0; mi < 2; mi++) {
                int arow = wm + mi * 16 + (lane & 15);
                int acol = k + (lane >> 4) * 8;
                uint32_t off = (uint32_t)(arow * LDA + acol) * 2;
                ldsm_x4(ah[mi], sb + PJ_AHI + off);
                ldsm_x4(al[mi], sb + PJ_ALO + off);
            }
            // B fragments: nj = 0,1 each covers 16 n (two n8 tiles)
            uint32_t bh[2][4], bl[2][4];
            #pragma unroll
            for (int nj = 0; nj < 2; nj++) {
                int brow = k + (lane & 15);
                int bcol = wn + nj * 16 + (lane >> 4) * 8;
                uint32_t off = (uint32_t)(brow * LDB + bcol) * 2;
                ldsm_x4_t(bh[nj], sb + PJ_BHI + off);
                ldsm_x4_t(bl[nj], sb + PJ_BLO + off);
            }

            #pragma unroll
            for (int mi = 0; mi < 2; mi++)
                #pragma unroll
                for (int ni = 0; ni < 4; ni++) {
                    int nj = ni >> 1, hf = (ni & 1) * 2;
                    mma16816(acc[mi][ni], ah[mi], bh[nj][hf], bh[nj][hf + 1]);
                    mma16816(acc[mi][ni], ah[mi], bl[nj][hf], bl[nj][hf + 1]);
                    mma16816(acc[mi][ni], al[mi], bh[nj][hf], bh[nj][hf + 1]);
                }
        }
    }

    // ---- epilogue: C frag -> gmem.  thread: gid=lane>>2 (row), t2=lane&3
    const int gid = lane >> 2, t2 = lane & 3;
    #pragma unroll
    for (int mi = 0; mi < 2; mi++) {
        #pragma unroll
        for (int ni = 0; ni < 4; ni++) {
            int r0r = row0 + wm + mi * 16 + gid;
            int cc  = col0 + wn + ni * 8 + t2 * 2;
            *(float2*)(out + (size_t)r0r * D_ + cc) =
                make_float2(acc[mi][ni][0], acc[mi][ni][1]);
            *(float2*)(out + (size_t)(r0r + 8) * D_ + cc) =
                make_float2(acc[mi][ni][2], acc[mi][ni][3]);
        }
    }
}

// ---------------------------------------------------------------------------
// Flash-style attention (byte-identical to the passing R1 kernel).
// ---------------------------------------------------------------------------
#define ATTN_SMEM (4 * 64 * 64 * 4 + 5 * 64 * 4)

__global__ void __launch_bounds__(256) attn_kernel(
        const int* __restrict__ mask, float* __restrict__ out)
{
    const int q0 = blockIdx.x * 64;
    const int hb = blockIdx.y;        // 0..79
    const int b  = hb & 7;
    const int h  = hb >> 3;

    extern __shared__ float smemf[];
    float (*Qs)[64]  = (float(*)[64])(smemf);
    float (*Kst)[64] = (float(*)[64])(smemf + 4096);
    float (*Vs)[64]  = (float(*)[64])(smemf + 8192);
    float (*Ss)[64]  = (float(*)[64])(smemf + 12288);
    float* m_sh  = smemf + 16384;
    float* l_sh  = m_sh + 64;
    float* al_sh = l_sh + 64;
    float* qm_sh = al_sh + 64;
    float* km_sh = qm_sh + 64;

    const int t  = threadIdx.x;
    const int tx = t & 15;
    const int ty = t >> 4;
    const int rowA = ty * 4;
    const int colA = tx * 4;
    const float scale = 0.125f;

    {
        size_t qbase = (size_t)(b * T_ + q0) * D_ + h * HD;
        #pragma unroll
        for (int e = t * 4; e < 4096; e += 1024) {
            int r = e >> 6, c = e & 63;
            *(float4*)&Qs[r][c] = *(const float4*)(g_Q + qbase + (size_t)r * D_ + c);
        }
    }
    if (t < 64) { m_sh[t] = -INFINITY; l_sh[t] = 0.0f; }
    __syncthreads();

    if (t < 64) {
        float s = 0.0f;
        #pragma unroll 8
        for (int c = 0; c < 64; c++) s += fabsf(Qs[t][c]);
        qm_sh[t] = (s != 0.0f) ? 1.0f : 0.0f;
    }

    float O[4][4] = {};
    const int nkt = (q0 == 0) ? (T_ / 64) : ((q0 >> 6) + 1);

    for (int kt = 0; kt < nkt; kt++) {
        const int k0 = kt * 64;
        __syncthreads();

        {
            size_t kbase = (size_t)(b * T_ + k0) * D_ + h * HD;
            #pragma unroll
            for (int e = t * 4; e < 4096; e += 1024) {
                int r = e >> 6, c = e & 63;
                float4 kv = *(const float4*)(g_K + kbase + (size_t)r * D_ + c);
                Kst[c + 0][r] = kv.x;
                Kst[c + 1][r] = kv.y;
                Kst[c + 2][r] = kv.z;
                Kst[c + 3][r] = kv.w;
                *(float4*)&Vs[r][c] = *(const float4*)(g_V + kbase + (size_t)r * D_ + c);
            }
        }
        __syncthreads();

        if (t < 64) {
            float s = 0.0f;
            #pragma unroll 8
            for (int kk = 0; kk < 64; kk++) s += fabsf(Kst[kk][t]);
            km_sh[t] = (s != 0.0f) ? 1.0f : 0.0f;
        }
        __syncthreads();

        float s[4][4] = {};
        #pragma unroll 8
        for (int kk = 0; kk < 64; kk++) {
            float a[4], bb[4];
            #pragma unroll
            for (int i = 0; i < 4; i++) a[i]  = Qs[rowA + i][kk];
            #pragma unroll
            for (int j = 0; j < 4; j++) bb[j] = Kst[kk][colA + j];
            #pragma unroll
            for (int i = 0; i < 4; i++)
                #pragma unroll
                for (int j = 0; j < 4; j++)
                    s[i][j] = fmaf(a[i], bb[j], s[i][j]);
        }

        #pragma unroll
        for (int i = 0; i < 4; i++) {
            int qrow = q0 + rowA + i;
            #pragma unroll
            for (int j = 0; j < 4; j++) {
                int kcol = k0 + colA + j;
                float v = s[i][j] * scale;
                if (km_sh[colA + j] == 0.0f) v = NEG_BIG;
                if (qrow <= kcol) v += -10000.0f;
                s[i][j] = v;
                Ss[rowA + i][colA + j] = v;
            }
        }
        __syncthreads();

        if (t < 64) {
            float tm = -INFINITY;
            #pragma unroll 8
            for (int c = 0; c < 64; c++) tm = fmaxf(tm, Ss[t][c]);
            float mold = m_sh[t];
            float mnew = fmaxf(mold, tm);
            m_sh[t]  = mnew;
            al_sh[t] = __expf(mold - mnew);
        }
        __syncthreads();

        float mrow[4], arow[4];
        #pragma unroll
        for (int i = 0; i < 4; i++) {
            mrow[i] = m_sh[rowA + i];
            arow[i] = al_sh[rowA + i];
        }
        #pragma unroll
        for (int i = 0; i < 4; i++)
            #pragma unroll
            for (int j = 0; j < 4; j++) {
                float p = __expf(s[i][j] - mrow[i]);
                Ss[rowA + i][colA + j] = p;
                O[i][j] *= arow[i];
            }
        __syncthreads();

        if (t < 64) {
            float sum = 0.0f;
            #pragma unroll 8
            for (int c = 0; c < 64; c++) sum += Ss[t][c];
            l_sh[t] = l_sh[t] * al_sh[t] + sum;
        }

        #pragma unroll 8
        for (int kk = 0; kk < 64; kk++) {
            float p[4], vv[4];
            #pragma unroll
            for (int i = 0; i < 4; i++) p[i]  = Ss[rowA + i][kk];
            #pragma unroll
            for (int j = 0; j < 4; j++) vv[j] = Vs[kk][colA + j];
            #pragma unroll
            for (int i = 0; i < 4; i++)
                #pragma unroll
                for (int j = 0; j < 4; j++)
                    O[i][j] = fmaf(p[i], vv[j], O[i][j]);
        }
    }

    __syncthreads();

    #pragma unroll
    for (int i = 0; i < 4; i++) {
        int qrow = q0 + rowA + i;
        float inv = 1.0f / l_sh[rowA + i];
        float mm  = qm_sh[rowA + i] * (float)mask[b * T_ + qrow];
        float f   = inv * mm;
        float4 v  = make_float4(O[i][0] * f, O[i][1] * f, O[i][2] * f, O[i][3] * f);
        *(float4*)(out + (size_t)(b * T_ + qrow) * D_ + h * HD + colA) = v;
    }
}

// ---------------------------------------------------------------------------
extern "C" void kernel_launch(void* const* d_in, const int* in_sizes, int n_in,
                              void* d_out, int out_size)
{
    const float* x    = (const float*)d_in[0];
    const int*   mask = (const int*)d_in[1];
    const float* Wq   = (const float*)d_in[2];
    const float* Wk   = (const float*)d_in[3];
    const float* Wv   = (const float*)d_in[4];
    float* out = (float*)d_out;

    cudaFuncSetAttribute(proj_tc_kernel,
                         cudaFuncAttributeMaxDynamicSharedMemorySize, PJ_SMEM);
    cudaFuncSetAttribute(attn_kernel,
                         cudaFuncAttributeMaxDynamicSharedMemorySize, ATTN_SMEM);

    dim3 gproj(D_ / 64, MTOT / 128, 3);
    proj_tc_kernel<<<gproj, 256, PJ_SMEM>>>(x, Wq, Wk, Wv);

    dim3 gattn(T_ / 64, H_ * B_);
    attn_kernel<<<gattn, 256, ATTN_SMEM>>>(mask, out);
}

// round 6
// speedup vs baseline: 2.8577x; 1.9991x over previous
#include <cuda_runtime.h>
#include <cuda_bf16.h>
#include <math.h>
#include <stdint.h>

#define B_   8
#define T_   1024
#define D_   640
#define H_   10
#define HD   64
#define MTOT (B_*T_)      // 8192
#define NEG_BIG (-4294967295.0f)   // -2^32+1

__device__ float g_Q[MTOT * D_];
__device__ float g_K[MTOT * D_];
__device__ float g_V[MTOT * D_];

// ===========================================================================
// Warp-level tensor-core helpers (baseline PTX, sm_80+, valid on sm_100)
// ===========================================================================
__device__ __forceinline__ uint32_t smem_u32(const void* p) {
    uint32_t a;
    asm("{ .reg .u64 t; cvta.to.shared.u64 t, %1; cvt.u32.u64 %0, t; }"
        : "=r"(a) : "l"(p));
    return a;
}

__device__ __forceinline__ void ldsm_x4(uint32_t* r, uint32_t addr) {
    asm volatile("ldmatrix.sync.aligned.m8n8.x4.shared.b16 {%0,%1,%2,%3}, [%4];"
        : "=r"(r[0]), "=r"(r[1]), "=r"(r[2]), "=r"(r[3]) : "r"(addr));
}
__device__ __forceinline__ void ldsm_x4_t(uint32_t* r, uint32_t addr) {
    asm volatile("ldmatrix.sync.aligned.m8n8.x4.trans.shared.b16 {%0,%1,%2,%3}, [%4];"
        : "=r"(r[0]), "=r"(r[1]), "=r"(r[2]), "=r"(r[3]) : "r"(addr));
}

__device__ __forceinline__ void mma16816(float* c, const uint32_t* a,
                                         uint32_t b0, uint32_t b1) {
    asm volatile(
        "mma.sync.aligned.m16n8k16.row.col.f32.bf16.bf16.f32 "
        "{%0,%1,%2,%3}, {%4,%5,%6,%7}, {%8,%9}, {%0,%1,%2,%3};"
        : "+f"(c[0]), "+f"(c[1]), "+f"(c[2]), "+f"(c[3])
        : "r"(a[0]), "r"(a[1]), "r"(a[2]), "r"(a[3]), "r"(b0), "r"(b1));
}

// split pair (a,b) into bf16 hi/lo, packed bf16x2 (a in low half)
__device__ __forceinline__ void bf16_split2(float a, float b,
                                            uint32_t& hi, uint32_t& lo) {
    __nv_bfloat16 ah = __float2bfloat16(a);
    __nv_bfloat16 bh = __float2bfloat16(b);
    __nv_bfloat16 al = __float2bfloat16(a - __bfloat162float(ah));
    __nv_bfloat16 bl = __float2bfloat16(b - __bfloat162float(bh));
    hi = (uint32_t)*(uint16_t*)&ah | ((uint32_t)*(uint16_t*)&bh << 16);
    lo = (uint32_t)*(uint16_t*)&al | ((uint32_t)*(uint16_t*)&bl << 16);
}

// ===========================================================================
// Projection: C[8192,640] = x @ W via mma.sync bf16 (unchanged from R5 WIN).
// ===========================================================================
#define LDA 72
#define LDB 72
#define PJ_AHI 0
#define PJ_ALO (128 * LDA * 2)
#define PJ_BHI (2 * 128 * LDA * 2)
#define PJ_BLO (2 * 128 * LDA * 2 + 64 * LDB * 2)
#define PJ_SMEM (2 * 128 * LDA * 2 + 2 * 64 * LDB * 2)  // 55296

__global__ void __launch_bounds__(256) proj_tc_kernel(
        const float* __restrict__ x,
        const float* __restrict__ Wq,
        const float* __restrict__ Wk,
        const float* __restrict__ Wv)
{
    const float* W;
    float* out;
    if (blockIdx.z == 0)      { W = Wq; out = g_Q; }
    else if (blockIdx.z == 1) { W = Wk; out = g_K; }
    else                      { W = Wv; out = g_V; }

    extern __shared__ char smem[];
    const uint32_t sb = smem_u32(smem);

    const int tid  = threadIdx.x;
    const int lane = tid & 31;
    const int wid  = tid >> 5;
    const int wm   = (wid & 3) * 32;
    const int wn   = (wid >> 2) * 32;

    const int row0 = blockIdx.y * 128;
    const int col0 = blockIdx.x * 64;

    float acc[2][4][4] = {};

    for (int c = 0; c < 10; c++) {
        const int k0 = c * 64;
        if (c > 0) __syncthreads();

        #pragma unroll
        for (int i = 0; i < 8; i++) {
            int lin = tid + i * 256;
            int r = lin >> 4, q = lin & 15;
            float4 v = *(const float4*)(x + (size_t)(row0 + r) * D_ + k0 + q * 4);
            uint2 hv, lv;
            bf16_split2(v.x, v.y, hv.x, lv.x);
            bf16_split2(v.z, v.w, hv.y, lv.y);
            uint32_t off = (uint32_t)(r * LDA + q * 4) * 2;
            *(uint2*)(smem + PJ_AHI + off) = hv;
            *(uint2*)(smem + PJ_ALO + off) = lv;
        }
        #pragma unroll
        for (int i = 0; i < 4; i++) {
            int lin = tid + i * 256;
            int kk = lin >> 4, nq = lin & 15;
            float4 v = *(const float4*)(W + (size_t)(k0 + kk) * D_ + col0 + nq * 4);
            uint2 hv, lv;
            bf16_split2(v.x, v.y, hv.x, lv.x);
            bf16_split2(v.z, v.w, hv.y, lv.y);
            uint32_t off = (uint32_t)(kk * LDB + nq * 4) * 2;
            *(uint2*)(smem + PJ_BHI + off) = hv;
            *(uint2*)(smem + PJ_BLO + off) = lv;
        }
        __syncthreads();

        #pragma unroll
        for (int ks = 0; ks < 4; ks++) {
            const int k = ks * 16;
            uint32_t ah[2][4], al[2][4];
            #pragma unroll
            for (int mi = 0; mi < 2; mi++) {
                int arow = wm + mi * 16 + (lane & 15);
                int acol = k + (lane >> 4) * 8;
                uint32_t off = (uint32_t)(arow * LDA + acol) * 2;
                ldsm_x4(ah[mi], sb + PJ_AHI + off);
                ldsm_x4(al[mi], sb + PJ_ALO + off);
            }
            uint32_t bh[2][4], bl[2][4];
            #pragma unroll
            for (int nj = 0; nj < 2; nj++) {
                int brow = k + (lane & 15);
                int bcol = wn + nj * 16 + (lane >> 4) * 8;
                uint32_t off = (uint32_t)(brow * LDB + bcol) * 2;
                ldsm_x4_t(bh[nj], sb + PJ_BHI + off);
                ldsm_x4_t(bl[nj], sb + PJ_BLO + off);
            }
            #pragma unroll
            for (int mi = 0; mi < 2; mi++)
                #pragma unroll
                for (int ni = 0; ni < 4; ni++) {
                    int nj = ni >> 1, hf = (ni & 1) * 2;
                    mma16816(acc[mi][ni], ah[mi], bh[nj][hf], bh[nj][hf + 1]);
                    mma16816(acc[mi][ni], ah[mi], bl[nj][hf], bl[nj][hf + 1]);
                    mma16816(acc[mi][ni], al[mi], bh[nj][hf], bh[nj][hf + 1]);
                }
        }
    }

    const int gid = lane >> 2, t2 = lane & 3;
    #pragma unroll
    for (int mi = 0; mi < 2; mi++) {
        #pragma unroll
        for (int ni = 0; ni < 4; ni++) {
            int r0r = row0 + wm + mi * 16 + gid;
            int cc  = col0 + wn + ni * 8 + t2 * 2;
            *(float2*)(out + (size_t)r0r * D_ + cc) =
                make_float2(acc[mi][ni][0], acc[mi][ni][1]);
            *(float2*)(out + (size_t)(r0r + 8) * D_ + cc) =
                make_float2(acc[mi][ni][2], acc[mi][ni][3]);
        }
    }
}

// ===========================================================================
// Tensor-core flash attention.  CTA = (64-q-tile, head, batch), 4 warps.
// Q/K/V tiles in smem as bf16 hi/lo (3-term split).  Scores & P in registers.
// ===========================================================================
#define TS 72
#define TILE_B (64 * TS * 2)        // 9216 bytes per bf16 tile
#define AT_QHI 0
#define AT_QLO (1 * TILE_B)
#define AT_KHI (2 * TILE_B)
#define AT_KLO (3 * TILE_B)
#define AT_VHI (4 * TILE_B)
#define AT_VLO (5 * TILE_B)
#define AT_KM  (6 * TILE_B)
#define AT_QM  (6 * TILE_B + 256)
#define ATTN2_SMEM (6 * TILE_B + 512)   // 55808

__global__ void __launch_bounds__(128, 3) attn_tc_kernel(
        const int* __restrict__ mask, float* __restrict__ out)
{
    const int q0 = blockIdx.x * 64;
    const int qt = blockIdx.x;
    const int hb = blockIdx.y;
    const int b  = hb & 7;
    const int h  = hb >> 3;

    extern __shared__ char sm[];
    const uint32_t sb = smem_u32(sm);
    float* km_sh = (float*)(sm + AT_KM);
    float* qm_sh = (float*)(sm + AT_QM);

    const int tid  = threadIdx.x;
    const int lane = tid & 31;
    const int w    = tid >> 5;

    // ---- load Q tile, split hi/lo
    {
        const float* src = g_Q + (size_t)(b * T_ + q0) * D_ + h * HD;
        #pragma unroll
        for (int i = 0; i < 8; i++) {
            int lin = tid + i * 128;
            int r = lin >> 4, c4 = lin & 15;
            float4 v = *(const float4*)(src + (size_t)r * D_ + c4 * 4);
            uint2 hv, lv;
            bf16_split2(v.x, v.y, hv.x, lv.x);
            bf16_split2(v.z, v.w, hv.y, lv.y);
            uint32_t off = (uint32_t)(r * TS + c4 * 4) * 2;
            *(uint2*)(sm + AT_QHI + off) = hv;
            *(uint2*)(sm + AT_QLO + off) = lv;
        }
    }
    __syncthreads();
    if (tid < 64) {
        const uint32_t* ph = (const uint32_t*)(sm + AT_QHI + tid * TS * 2);
        const uint32_t* pl = (const uint32_t*)(sm + AT_QLO + tid * TS * 2);
        uint32_t o = 0;
        #pragma unroll 8
        for (int c = 0; c < 32; c++) o |= (ph[c] | pl[c]) & 0x7FFF7FFFu;
        qm_sh[tid] = o ? 1.0f : 0.0f;
    }

    float m0 = -INFINITY, m1 = -INFINITY, l0 = 0.0f, l1 = 0.0f;
    float O[8][4] = {};

    const int nkt = (q0 == 0) ? (T_ / 64) : (qt + 1);

    for (int kt = 0; kt < nkt; kt++) {
        const int k0 = kt * 64;
        const bool fullmask = kt > qt;    // only q-tile 0
        const bool diag = (kt == qt);

        __syncthreads();   // previous iteration's K/V readers done

        // ---- load K and V tiles, split hi/lo
        {
            const float* ksrc = g_K + (size_t)(b * T_ + k0) * D_ + h * HD;
            const float* vsrc = g_V + (size_t)(b * T_ + k0) * D_ + h * HD;
            #pragma unroll
            for (int i = 0; i < 8; i++) {
                int lin = tid + i * 128;
                int r = lin >> 4, c4 = lin & 15;
                uint32_t off = (uint32_t)(r * TS + c4 * 4) * 2;
                float4 kv = *(const float4*)(ksrc + (size_t)r * D_ + c4 * 4);
                uint2 hv, lv;
                bf16_split2(kv.x, kv.y, hv.x, lv.x);
                bf16_split2(kv.z, kv.w, hv.y, lv.y);
                *(uint2*)(sm + AT_KHI + off) = hv;
                *(uint2*)(sm + AT_KLO + off) = lv;
                float4 vv = *(const float4*)(vsrc + (size_t)r * D_ + c4 * 4);
                bf16_split2(vv.x, vv.y, hv.x, lv.x);
                bf16_split2(vv.z, vv.w, hv.y, lv.y);
                *(uint2*)(sm + AT_VHI + off) = hv;
                *(uint2*)(sm + AT_VLO + off) = lv;
            }
        }
        __syncthreads();

        // ---- key padding mask (bit-OR; sign bits stripped)
        int rowok = 1;
        if (tid < 64) {
            const uint32_t* ph = (const uint32_t*)(sm + AT_KHI + tid * TS * 2);
            const uint32_t* pl = (const uint32_t*)(sm + AT_KLO + tid * TS * 2);
            uint32_t o = 0;
            #pragma unroll 8
            for (int c = 0; c < 32; c++) o |= (ph[c] | pl[c]) & 0x7FFF7FFFu;
            km_sh[tid] = o ? 1.0f : 0.0f;
            rowok = o ? 1 : 0;
        }
        const int allkm = __syncthreads_and(rowok);

        // ---- S = Q K^T (3-term bf16 split), S in C-fragments s[8][4]
        float s[8][4] = {};
        #pragma unroll
        for (int ks = 0; ks < 4; ks++) {
            uint32_t ah[4], al[4];
            uint32_t aoff = (uint32_t)((16 * w + (lane & 15)) * TS
                                       + ks * 16 + (lane >> 4) * 8) * 2;
            ldsm_x4(ah, sb + AT_QHI + aoff);
            ldsm_x4(al, sb + AT_QLO + aoff);
            #pragma unroll
            for (int kg = 0; kg < 4; kg++) {
                uint32_t bh[4], bl[4];
                uint32_t boff = (uint32_t)((kg * 16 + (lane & 15)) * TS
                                           + ks * 16 + (lane >> 4) * 8) * 2;
                ldsm_x4(bh, sb + AT_KHI + boff);
                ldsm_x4(bl, sb + AT_KLO + boff);
                mma16816(s[2 * kg],     ah, bh[0], bh[2]);
                mma16816(s[2 * kg],     ah, bl[0], bl[2]);
                mma16816(s[2 * kg],     al, bh[0], bh[2]);
                mma16816(s[2 * kg + 1], ah, bh[1], bh[3]);
                mma16816(s[2 * kg + 1], ah, bl[1], bl[3]);
                mma16816(s[2 * kg + 1], al, bh[1], bh[3]);
            }
        }

        // ---- masks (scale, key-padding, directional)
        const int rbase = q0 + 16 * w + (lane >> 2);
        const int cq = 2 * (lane & 3);
        #pragma unroll
        for (int j = 0; j < 8; j++) {
            #pragma unroll
            for (int e = 0; e < 4; e++) {
                int row = rbase + ((e >> 1) << 3);
                int col = k0 + 8 * j + cq + (e & 1);
                float v = s[j][e] * 0.125f;
                if (!allkm && km_sh[8 * j + cq + (e & 1)] == 0.0f) v = NEG_BIG;
                if (fullmask) v += -10000.0f;
                else if (diag && row <= col) v += -10000.0f;
                s[j][e] = v;
            }
        }

        // ---- online softmax: row max, alpha, exp, row sum
        float tmax0 = -INFINITY, tmax1 = -INFINITY;
        #pragma unroll
        for (int j = 0; j < 8; j++) {
            tmax0 = fmaxf(tmax0, fmaxf(s[j][0], s[j][1]));
            tmax1 = fmaxf(tmax1, fmaxf(s[j][2], s[j][3]));
        }
        tmax0 = fmaxf(tmax0, __shfl_xor_sync(0xffffffffu, tmax0, 1));
        tmax0 = fmaxf(tmax0, __shfl_xor_sync(0xffffffffu, tmax0, 2));
        tmax1 = fmaxf(tmax1, __shfl_xor_sync(0xffffffffu, tmax1, 1));
        tmax1 = fmaxf(tmax1, __shfl_xor_sync(0xffffffffu, tmax1, 2));

        float mn0 = fmaxf(m0, tmax0), mn1 = fmaxf(m1, tmax1);
        float a0 = __expf(m0 - mn0), a1 = __expf(m1 - mn1);
        m0 = mn0; m1 = mn1;

        float rs0 = 0.0f, rs1 = 0.0f;
        #pragma unroll
        for (int j = 0; j < 8; j++) {
            float p0 = __expf(s[j][0] - m0);
            float p1 = __expf(s[j][1] - m0);
            float p2 = __expf(s[j][2] - m1);
            float p3 = __expf(s[j][3] - m1);
            s[j][0] = p0; s[j][1] = p1; s[j][2] = p2; s[j][3] = p3;
            rs0 += p0 + p1; rs1 += p2 + p3;
        }
        rs0 += __shfl_xor_sync(0xffffffffu, rs0, 1);
        rs0 += __shfl_xor_sync(0xffffffffu, rs0, 2);
        rs1 += __shfl_xor_sync(0xffffffffu, rs1, 1);
        rs1 += __shfl_xor_sync(0xffffffffu, rs1, 2);
        l0 = l0 * a0 + rs0;
        l1 = l1 * a1 + rs1;

        #pragma unroll
        for (int j = 0; j < 8; j++) {
            O[j][0] *= a0; O[j][1] *= a0;
            O[j][2] *= a1; O[j][3] *= a1;
        }

        // ---- O += P @ V  (P packed in registers, V via ldmatrix.trans)
        #pragma unroll
        for (int ks = 0; ks < 4; ks++) {
            uint32_t pah[4], pal[4];
            bf16_split2(s[2 * ks][0],     s[2 * ks][1],     pah[0], pal[0]);
            bf16_split2(s[2 * ks][2],     s[2 * ks][3],     pah[1], pal[1]);
            bf16_split2(s[2 * ks + 1][0], s[2 * ks + 1][1], pah[2], pal[2]);
            bf16_split2(s[2 * ks + 1][2], s[2 * ks + 1][3], pah[3], pal[3]);
            #pragma unroll
            for (int dg = 0; dg < 4; dg++) {
                uint32_t vh[4], vl[4];
                uint32_t voff = (uint32_t)((ks * 16 + (lane & 15)) * TS
                                           + dg * 16 + (lane >> 4) * 8) * 2;
                ldsm_x4_t(vh, sb + AT_VHI + voff);
                ldsm_x4_t(vl, sb + AT_VLO + voff);
                mma16816(O[2 * dg],     pah, vh[0], vh[1]);
                mma16816(O[2 * dg],     pah, vl[0], vl[1]);
                mma16816(O[2 * dg],     pal, vh[0], vh[1]);
                mma16816(O[2 * dg + 1], pah, vh[2], vh[3]);
                mma16816(O[2 * dg + 1], pah, vl[2], vl[3]);
                mma16816(O[2 * dg + 1], pal, vh[2], vh[3]);
            }
        }
    }

    // ---- epilogue: normalize, query mask, final row mask, store
    const int row0g = q0 + 16 * w + (lane >> 2);
    const int row1g = row0g + 8;
    const float f0 = (1.0f / l0) * qm_sh[row0g - q0] * (float)mask[b * T_ + row0g];
    const float f1 = (1.0f / l1) * qm_sh[row1g - q0] * (float)mask[b * T_ + row1g];
    #pragma unroll
    for (int j = 0; j < 8; j++) {
        int col = h * HD + 8 * j + 2 * (lane & 3);
        *(float2*)(out + (size_t)(b * T_ + row0g) * D_ + col) =
            make_float2(O[j][0] * f0, O[j][1] * f0);
        *(float2*)(out + (size_t)(b * T_ + row1g) * D_ + col) =
            make_float2(O[j][2] * f1, O[j][3] * f1);
    }
}

// ---------------------------------------------------------------------------
extern "C" void kernel_launch(void* const* d_in, const int* in_sizes, int n_in,
                              void* d_out, int out_size)
{
    const float* x    = (const float*)d_in[0];
    const int*   mask = (const int*)d_in[1];
    const float* Wq   = (const float*)d_in[2];
    const float* Wk   = (const float*)d_in[3];
    const float* Wv   = (const float*)d_in[4];
    float* out = (float*)d_out;

    cudaFuncSetAttribute(proj_tc_kernel,
                         cudaFuncAttributeMaxDynamicSharedMemorySize, PJ_SMEM);
    cudaFuncSetAttribute(attn_tc_kernel,
                         cudaFuncAttributeMaxDynamicSharedMemorySize, ATTN2_SMEM);

    dim3 gproj(D_ / 64, MTOT / 128, 3);
    proj_tc_kernel<<<gproj, 256, PJ_SMEM>>>(x, Wq, Wk, Wv);

    dim3 gattn(T_ / 64, H_ * B_);
    attn_tc_kernel<<<gattn, 128, ATTN2_SMEM>>>(mask, out);
}

// round 8
// speedup vs baseline: 2.8700x; 1.0043x over previous
#include <cuda_runtime.h>
#include <cuda_bf16.h>
#include <math.h>
#include <stdint.h>

#define B_   8
#define T_   1024
#define D_   640
#define H_   10
#define HD   64
#define MTOT (B_*T_)      // 8192
#define DW   (D_/2)       // 320 uint32 per row (packed bf16x2)
#define NEG_BIG (-4294967295.0f)   // -2^32+1

// Q/K/V stored as packed bf16x2 hi/lo planes (written by proj, read by attn)
__device__ uint32_t g_Qh[MTOT * DW];
__device__ uint32_t g_Ql[MTOT * DW];
__device__ uint32_t g_Kh[MTOT * DW];
__device__ uint32_t g_Kl[MTOT * DW];
__device__ uint32_t g_Vh[MTOT * DW];
__device__ uint32_t g_Vl[MTOT * DW];

// ===========================================================================
// Warp-level tensor-core helpers (baseline PTX, sm_80+, valid on sm_100)
// ===========================================================================
__device__ __forceinline__ uint32_t smem_u32(const void* p) {
    uint32_t a;
    asm("{ .reg .u64 t; cvta.to.shared.u64 t, %1; cvt.u32.u64 %0, t; }"
        : "=r"(a) : "l"(p));
    return a;
}

__device__ __forceinline__ void ldsm_x4(uint32_t* r, uint32_t addr) {
    asm volatile("ldmatrix.sync.aligned.m8n8.x4.shared.b16 {%0,%1,%2,%3}, [%4];"
        : "=r"(r[0]), "=r"(r[1]), "=r"(r[2]), "=r"(r[3]) : "r"(addr));
}
__device__ __forceinline__ void ldsm_x4_t(uint32_t* r, uint32_t addr) {
    asm volatile("ldmatrix.sync.aligned.m8n8.x4.trans.shared.b16 {%0,%1,%2,%3}, [%4];"
        : "=r"(r[0]), "=r"(r[1]), "=r"(r[2]), "=r"(r[3]) : "r"(addr));
}

__device__ __forceinline__ void mma16816(float* c, const uint32_t* a,
                                         uint32_t b0, uint32_t b1) {
    asm volatile(
        "mma.sync.aligned.m16n8k16.row.col.f32.bf16.bf16.f32 "
        "{%0,%1,%2,%3}, {%4,%5,%6,%7}, {%8,%9}, {%0,%1,%2,%3};"
        : "+f"(c[0]), "+f"(c[1]), "+f"(c[2]), "+f"(c[3])
        : "r"(a[0]), "r"(a[1]), "r"(a[2]), "r"(a[3]), "r"(b0), "r"(b1));
}

// split pair (a,b) into bf16 hi/lo, packed bf16x2 (a in low half)
__device__ __forceinline__ void bf16_split2(float a, float b,
                                            uint32_t& hi, uint32_t& lo) {
    __nv_bfloat16 ah = __float2bfloat16(a);
    __nv_bfloat16 bh = __float2bfloat16(b);
    __nv_bfloat16 al = __float2bfloat16(a - __bfloat162float(ah));
    __nv_bfloat16 bl = __float2bfloat16(b - __bfloat162float(bh));
    hi = (uint32_t)*(uint16_t*)&ah | ((uint32_t)*(uint16_t*)&bh << 16);
    lo = (uint32_t)*(uint16_t*)&al | ((uint32_t)*(uint16_t*)&bl << 16);
}

__device__ __forceinline__ void cp16(uint32_t dst, const void* src) {
    asm volatile("cp.async.cg.shared.global [%0], [%1], 16;"
        :: "r"(dst), "l"(src));
}
#define CP_COMMIT_WAIT() \
    asm volatile("cp.async.commit_group;\n\tcp.async.wait_group 0;" ::: "memory")

// ===========================================================================
// Projection: C[8192,640] = x @ W via mma.sync bf16 (3-term hi/lo split).
// Epilogue converts to bf16 hi/lo and stores packed planes for attention.
// ===========================================================================
#define LDA 72
#define LDB 72
#define PJ_AHI 0
#define PJ_ALO (128 * LDA * 2)
#define PJ_BHI (2 * 128 * LDA * 2)
#define PJ_BLO (2 * 128 * LDA * 2 + 64 * LDB * 2)
#define PJ_SMEM (2 * 128 * LDA * 2 + 2 * 64 * LDB * 2)  // 55296

__global__ void __launch_bounds__(256) proj_tc_kernel(
        const float* __restrict__ x,
        const float* __restrict__ Wq,
        const float* __restrict__ Wk,
        const float* __restrict__ Wv)
{
    const float* W;
    uint32_t* outh;
    uint32_t* outl;
    if (blockIdx.z == 0)      { W = Wq; outh = g_Qh; outl = g_Ql; }
    else if (blockIdx.z == 1) { W = Wk; outh = g_Kh; outl = g_Kl; }
    else                      { W = Wv; outh = g_Vh; outl = g_Vl; }

    extern __shared__ char smem[];
    const uint32_t sb = smem_u32(smem);

    const int tid  = threadIdx.x;
    const int lane = tid & 31;
    const int wid  = tid >> 5;
    const int wm   = (wid & 3) * 32;
    const int wn   = (wid >> 2) * 32;

    const int row0 = blockIdx.y * 128;
    const int col0 = blockIdx.x * 64;

    float acc[2][4][4] = {};

    for (int c = 0; c < 10; c++) {
        const int k0 = c * 64;
        if (c > 0) __syncthreads();

        #pragma unroll
        for (int i = 0; i < 8; i++) {
            int lin = tid + i * 256;
            int r = lin >> 4, q = lin & 15;
            float4 v = *(const float4*)(x + (size_t)(row0 + r) * D_ + k0 + q * 4);
            uint2 hv, lv;
            bf16_split2(v.x, v.y, hv.x, lv.x);
            bf16_split2(v.z, v.w, hv.y, lv.y);
            uint32_t off = (uint32_t)(r * LDA + q * 4) * 2;
            *(uint2*)(smem + PJ_AHI + off) = hv;
            *(uint2*)(smem + PJ_ALO + off) = lv;
        }
        #pragma unroll
        for (int i = 0; i < 4; i++) {
            int lin = tid + i * 256;
            int kk = lin >> 4, nq = lin & 15;
            float4 v = *(const float4*)(W + (size_t)(k0 + kk) * D_ + col0 + nq * 4);
            uint2 hv, lv;
            bf16_split2(v.x, v.y, hv.x, lv.x);
            bf16_split2(v.z, v.w, hv.y, lv.y);
            uint32_t off = (uint32_t)(kk * LDB + nq * 4) * 2;
            *(uint2*)(smem + PJ_BHI + off) = hv;
            *(uint2*)(smem + PJ_BLO + off) = lv;
        }
        __syncthreads();

        #pragma unroll
        for (int ks = 0; ks < 4; ks++) {
            const int k = ks * 16;
            uint32_t ah[2][4], al[2][4];
            #pragma unroll
            for (int mi = 0; mi < 2; mi++) {
                int arow = wm + mi * 16 + (lane & 15);
                int acol = k + (lane >> 4) * 8;
                uint32_t off = (uint32_t)(arow * LDA + acol) * 2;
                ldsm_x4(ah[mi], sb + PJ_AHI + off);
                ldsm_x4(al[mi], sb + PJ_ALO + off);
            }
            uint32_t bh[2][4], bl[2][4];
            #pragma unroll
            for (int nj = 0; nj < 2; nj++) {
                int brow = k + (lane & 15);
                int bcol = wn + nj * 16 + (lane >> 4) * 8;
                uint32_t off = (uint32_t)(brow * LDB + bcol) * 2;
                ldsm_x4_t(bh[nj], sb + PJ_BHI + off);
                ldsm_x4_t(bl[nj], sb + PJ_BLO + off);
            }
            #pragma unroll
            for (int mi = 0; mi < 2; mi++)
                #pragma unroll
                for (int ni = 0; ni < 4; ni++) {
                    int nj = ni >> 1, hf = (ni & 1) * 2;
                    mma16816(acc[mi][ni], ah[mi], bh[nj][hf], bh[nj][hf + 1]);
                    mma16816(acc[mi][ni], ah[mi], bl[nj][hf], bl[nj][hf + 1]);
                    mma16816(acc[mi][ni], al[mi], bh[nj][hf], bh[nj][hf + 1]);
                }
        }
    }

    // ---- epilogue: split to bf16 hi/lo planes, packed bf16x2 per col pair
    const int gid = lane >> 2, t2 = lane & 3;
    #pragma unroll
    for (int mi = 0; mi < 2; mi++) {
        #pragma unroll
        for (int ni = 0; ni < 4; ni++) {
            int r0r = row0 + wm + mi * 16 + gid;
            int cc  = col0 + wn + ni * 8 + t2 * 2;   // even
            uint32_t h0, l0, h1, l1;
            bf16_split2(acc[mi][ni][0], acc[mi][ni][1], h0, l0);
            bf16_split2(acc[mi][ni][2], acc[mi][ni][3], h1, l1);
            size_t i0 = (size_t)r0r * DW + (cc >> 1);
            size_t i1 = (size_t)(r0r + 8) * DW + (cc >> 1);
            outh[i0] = h0; outl[i0] = l0;
            outh[i1] = h1; outl[i1] = l1;
        }
    }
}

// ===========================================================================
// Tensor-core flash attention.  CTA = (64-q-tile, head, batch), 4 warps.
// Q/K/V tiles arrive pre-split as bf16 hi/lo; smem fill is pure cp.async.
// ===========================================================================
#define TS 72
#define TILE_B (64 * TS * 2)        // 9216 bytes per bf16 tile
#define AT_QHI 0
#define AT_QLO (1 * TILE_B)
#define AT_KHI (2 * TILE_B)
#define AT_KLO (3 * TILE_B)
#define AT_VHI (4 * TILE_B)
#define AT_VLO (5 * TILE_B)
#define AT_KM  (6 * TILE_B)
#define AT_QM  (6 * TILE_B + 256)
#define ATTN2_SMEM (6 * TILE_B + 512)   // 55808

__global__ void __launch_bounds__(128, 3) attn_tc_kernel(
        const int* __restrict__ mask, float* __restrict__ out)
{
    const int q0 = blockIdx.x * 64;
    const int qt = blockIdx.x;
    const int hb = blockIdx.y;
    const int b  = hb & 7;
    const int h  = hb >> 3;

    extern __shared__ char sm[];
    const uint32_t sb = smem_u32(sm);
    float* km_sh = (float*)(sm + AT_KM);
    float* qm_sh = (float*)(sm + AT_QM);

    const int tid  = threadIdx.x;
    const int lane = tid & 31;
    const int w    = tid >> 5;

    // ---- load Q tile (hi/lo planes) via cp.async: 2 planes x 64 rows x 8 segs
    {
        const uint32_t* qh = g_Qh + (size_t)(b * T_ + q0) * DW + h * 32;
        const uint32_t* ql = g_Ql + (size_t)(b * T_ + q0) * DW + h * 32;
        #pragma unroll
        for (int i = 0; i < 8; i++) {
            int lin = tid + i * 128;        // 0..1023
            int plane = lin >> 9;           // 0=hi, 1=lo
            int rem = lin & 511;
            int r = rem >> 3, seg = rem & 7;
            const uint32_t* src = (plane ? ql : qh) + (size_t)r * DW + seg * 4;
            uint32_t dst = sb + (plane ? AT_QLO : AT_QHI) + r * 144 + seg * 16;
            cp16(dst, src);
        }
        CP_COMMIT_WAIT();
    }
    __syncthreads();
    if (tid < 64) {
        const uint32_t* ph = (const uint32_t*)(sm + AT_QHI + tid * TS * 2);
        const uint32_t* pl = (const uint32_t*)(sm + AT_QLO + tid * TS * 2);
        uint32_t o = 0;
        #pragma unroll 8
        for (int c = 0; c < 32; c++) o |= (ph[c] | pl[c]) & 0x7FFF7FFFu;
        qm_sh[tid] = o ? 1.0f : 0.0f;
    }

    float m0 = -INFINITY, m1 = -INFINITY, l0 = 0.0f, l1 = 0.0f;
    float O[8][4] = {};

    const int nkt = (q0 == 0) ? (T_ / 64) : (qt + 1);

    for (int kt = 0; kt < nkt; kt++) {
        const int k0 = kt * 64;
        const bool fullmask = kt > qt;    // only q-tile 0
        const bool diag = (kt == qt);

        __syncthreads();   // previous iteration's K/V readers done

        // ---- load K and V tiles: 4 planes x 64 rows x 8 segs = 2048 cp16
        {
            const size_t base = (size_t)(b * T_ + k0) * DW + h * 32;
            const uint32_t* pk[4] = { g_Kh + base, g_Kl + base,
                                      g_Vh + base, g_Vl + base };
            const uint32_t doff[4] = { AT_KHI, AT_KLO, AT_VHI, AT_VLO };
            #pragma unroll
            for (int i = 0; i < 16; i++) {
                int lin = tid + i * 128;    // 0..2047
                int plane = lin >> 9;       // 0..3 (constant per i)
                int rem = lin & 511;
                int r = rem >> 3, seg = rem & 7;
                cp16(sb + doff[plane] + r * 144 + seg * 16,
                     pk[plane] + (size_t)r * DW + seg * 4);
            }
            CP_COMMIT_WAIT();
        }
        __syncthreads();

        // ---- key padding mask (bit-OR; sign bits stripped)
        int rowok = 1;
        if (tid < 64) {
            const uint32_t* ph = (const uint32_t*)(sm + AT_KHI + tid * TS * 2);
            const uint32_t* pl = (const uint32_t*)(sm + AT_KLO + tid * TS * 2);
            uint32_t o = 0;
            #pragma unroll 8
            for (int c = 0; c < 32; c++) o |= (ph[c] | pl[c]) & 0x7FFF7FFFu;
            km_sh[tid] = o ? 1.0f : 0.0f;
            rowok = o ? 1 : 0;
        }
        const int allkm = __syncthreads_and(rowok);

        // ---- S = Q K^T (3-term bf16 split), S in C-fragments s[8][4]
        float s[8][4] = {};
        #pragma unroll
        for (int ks = 0; ks < 4; ks++) {
            uint32_t ah[4], al[4];
            uint32_t aoff = (uint32_t)((16 * w + (lane & 15)) * TS
                                       + ks * 16 + (lane >> 4) * 8) * 2;
            ldsm_x4(ah, sb + AT_QHI + aoff);
            ldsm_x4(al, sb + AT_QLO + aoff);
            #pragma unroll
            for (int kg = 0; kg < 4; kg++) {
                uint32_t bh[4], bl[4];
                uint32_t boff = (uint32_t)((kg * 16 + (lane & 15)) * TS
                                           + ks * 16 + (lane >> 4) * 8) * 2;
                ldsm_x4(bh, sb + AT_KHI + boff);
                ldsm_x4(bl, sb + AT_KLO + boff);
                mma16816(s[2 * kg],     ah, bh[0], bh[2]);
                mma16816(s[2 * kg],     ah, bl[0], bl[2]);
                mma16816(s[2 * kg],     al, bh[0], bh[2]);
                mma16816(s[2 * kg + 1], ah, bh[1], bh[3]);
                mma16816(s[2 * kg + 1], ah, bl[1], bl[3]);
                mma16816(s[2 * kg + 1], al, bh[1], bh[3]);
            }
        }

        // ---- masks (scale, key-padding, directional)
        const int rbase = q0 + 16 * w + (lane >> 2);
        const int cq = 2 * (lane & 3);
        #pragma unroll
        for (int j = 0; j < 8; j++) {
            #pragma unroll
            for (int e = 0; e < 4; e++) {
                int row = rbase + ((e >> 1) << 3);
                int col = k0 + 8 * j + cq + (e & 1);
                float v = s[j][e] * 0.125f;
                if (!allkm && km_sh[8 * j + cq + (e & 1)] == 0.0f) v = NEG_BIG;
                if (fullmask) v += -10000.0f;
                else if (diag && row <= col) v += -10000.0f;
                s[j][e] = v;
            }
        }

        // ---- online softmax: row max, alpha, exp, row sum
        float tmax0 = -INFINITY, tmax1 = -INFINITY;
        #pragma unroll
        for (int j = 0; j < 8; j++) {
            tmax0 = fmaxf(tmax0, fmaxf(s[j][0], s[j][1]));
            tmax1 = fmaxf(tmax1, fmaxf(s[j][2], s[j][3]));
        }
        tmax0 = fmaxf(tmax0, __shfl_xor_sync(0xffffffffu, tmax0, 1));
        tmax0 = fmaxf(tmax0, __shfl_xor_sync(0xffffffffu, tmax0, 2));
        tmax1 = fmaxf(tmax1, __shfl_xor_sync(0xffffffffu, tmax1, 1));
        tmax1 = fmaxf(tmax1, __shfl_xor_sync(0xffffffffu, tmax1, 2));

        float mn0 = fmaxf(m0, tmax0), mn1 = fmaxf(m1, tmax1);
        float a0 = __expf(m0 - mn0), a1 = __expf(m1 - mn1);
        m0 = mn0; m1 = mn1;

        float rs0 = 0.0f, rs1 = 0.0f;
        #pragma unroll
        for (int j = 0; j < 8; j++) {
            float p0 = __expf(s[j][0] - m0);
            float p1 = __expf(s[j][1] - m0);
            float p2 = __expf(s[j][2] - m1);
            float p3 = __expf(s[j][3] - m1);
            s[j][0] = p0; s[j][1] = p1; s[j][2] = p2; s[j][3] = p3;
            rs0 += p0 + p1; rs1 += p2 + p3;
        }
        rs0 += __shfl_xor_sync(0xffffffffu, rs0, 1);
        rs0 += __shfl_xor_sync(0xffffffffu, rs0, 2);
        rs1 += __shfl_xor_sync(0xffffffffu, rs1, 1);
        rs1 += __shfl_xor_sync(0xffffffffu, rs1, 2);
        l0 = l0 * a0 + rs0;
        l1 = l1 * a1 + rs1;

        #pragma unroll
        for (int j = 0; j < 8; j++) {
            O[j][0] *= a0; O[j][1] *= a0;
            O[j][2] *= a1; O[j][3] *= a1;
        }

        // ---- O += P @ V  (P packed in registers, V via ldmatrix.trans)
        #pragma unroll
        for (int ks = 0; ks < 4; ks++) {
            uint32_t pah[4], pal[4];
            bf16_split2(s[2 * ks][0],     s[2 * ks][1],     pah[0], pal[0]);
            bf16_split2(s[2 * ks][2],     s[2 * ks][3],     pah[1], pal[1]);
            bf16_split2(s[2 * ks + 1][0], s[2 * ks + 1][1], pah[2], pal[2]);
            bf16_split2(s[2 * ks + 1][2], s[2 * ks + 1][3], pah[3], pal[3]);
            #pragma unroll
            for (int dg = 0; dg < 4; dg++) {
                uint32_t vh[4], vl[4];
                uint32_t voff = (uint32_t)((ks * 16 + (lane & 15)) * TS
                                           + dg * 16 + (lane >> 4) * 8) * 2;
                ldsm_x4_t(vh, sb + AT_VHI + voff);
                ldsm_x4_t(vl, sb + AT_VLO + voff);
                mma16816(O[2 * dg],     pah, vh[0], vh[1]);
                mma16816(O[2 * dg],     pah, vl[0], vl[1]);
                mma16816(O[2 * dg],     pal, vh[0], vh[1]);
                mma16816(O[2 * dg + 1], pah, vh[2], vh[3]);
                mma16816(O[2 * dg + 1], pah, vl[2], vl[3]);
                mma16816(O[2 * dg + 1], pal, vh[2], vh[3]);
            }
        }
    }

    // ---- epilogue: normalize, query mask, final row mask, store
    const int row0g = q0 + 16 * w + (lane >> 2);
    const int row1g = row0g + 8;
    const float f0 = (1.0f / l0) * qm_sh[row0g - q0] * (float)mask[b * T_ + row0g];
    const float f1 = (1.0f / l1) * qm_sh[row1g - q0] * (float)mask[b * T_ + row1g];
    #pragma unroll
    for (int j = 0; j < 8; j++) {
        int col = h * HD + 8 * j + 2 * (lane & 3);
        *(float2*)(out + (size_t)(b * T_ + row0g) * D_ + col) =
            make_float2(O[j][0] * f0, O[j][1] * f0);
        *(float2*)(out + (size_t)(b * T_ + row1g) * D_ + col) =
            make_float2(O[j][2] * f1, O[j][3] * f1);
    }
}

// ---------------------------------------------------------------------------
extern "C" void kernel_launch(void* const* d_in, const int* in_sizes, int n_in,
                              void* d_out, int out_size)
{
    const float* x    = (const float*)d_in[0];
    const int*   mask = (const int*)d_in[1];
    const float* Wq   = (const float*)d_in[2];
    const float* Wk   = (const float*)d_in[3];
    const float* Wv   = (const float*)d_in[4];
    float* out = (float*)d_out;

    cudaFuncSetAttribute(proj_tc_kernel,
                         cudaFuncAttributeMaxDynamicSharedMemorySize, PJ_SMEM);
    cudaFuncSetAttribute(attn_tc_kernel,
                         cudaFuncAttributeMaxDynamicSharedMemorySize, ATTN2_SMEM);

    dim3 gproj(D_ / 64, MTOT / 128, 3);
    proj_tc_kernel<<<gproj, 256, PJ_SMEM>>>(x, Wq, Wk, Wv);

    dim3 gattn(T_ / 64, H_ * B_);
    attn_tc_kernel<<<gattn, 128, ATTN2_SMEM>>>(mask, out);
}

// round 9
// speedup vs baseline: 2.9523x; 1.0287x over previous
#include <cuda_runtime.h>
#include <cuda_bf16.h>
#include <math.h>
#include <stdint.h>

#define B_   8
#define T_   1024
#define D_   640
#define H_   10
#define HD   64
#define MTOT (B_*T_)      // 8192
#define DW   (D_/2)       // 320 u32 per row (packed bf16x2)
#define WN   (640*320)    // u32 per weight plane
#define NEG_BIG (-4294967295.0f)

// pre-split inputs (written by split_inputs)
__device__ uint32_t g_Xh[MTOT * DW];
__device__ uint32_t g_Xl[MTOT * DW];
__device__ uint32_t g_Wh[3 * WN];
__device__ uint32_t g_Wl[3 * WN];
// Q/K/V packed bf16x2 hi/lo planes (written by proj, read by attn)
__device__ uint32_t g_Qh[MTOT * DW];
__device__ uint32_t g_Ql[MTOT * DW];
__device__ uint32_t g_Kh[MTOT * DW];
__device__ uint32_t g_Kl[MTOT * DW];
__device__ uint32_t g_Vh[MTOT * DW];
__device__ uint32_t g_Vl[MTOT * DW];

// ===========================================================================
__device__ __forceinline__ uint32_t smem_u32(const void* p) {
    uint32_t a;
    asm("{ .reg .u64 t; cvta.to.shared.u64 t, %1; cvt.u32.u64 %0, t; }"
        : "=r"(a) : "l"(p));
    return a;
}
__device__ __forceinline__ void ldsm_x4(uint32_t* r, uint32_t addr) {
    asm volatile("ldmatrix.sync.aligned.m8n8.x4.shared.b16 {%0,%1,%2,%3}, [%4];"
        : "=r"(r[0]), "=r"(r[1]), "=r"(r[2]), "=r"(r[3]) : "r"(addr));
}
__device__ __forceinline__ void ldsm_x4_t(uint32_t* r, uint32_t addr) {
    asm volatile("ldmatrix.sync.aligned.m8n8.x4.trans.shared.b16 {%0,%1,%2,%3}, [%4];"
        : "=r"(r[0]), "=r"(r[1]), "=r"(r[2]), "=r"(r[3]) : "r"(addr));
}
__device__ __forceinline__ void mma16816(float* c, const uint32_t* a,
                                         uint32_t b0, uint32_t b1) {
    asm volatile(
        "mma.sync.aligned.m16n8k16.row.col.f32.bf16.bf16.f32 "
        "{%0,%1,%2,%3}, {%4,%5,%6,%7}, {%8,%9}, {%0,%1,%2,%3};"
        : "+f"(c[0]), "+f"(c[1]), "+f"(c[2]), "+f"(c[3])
        : "r"(a[0]), "r"(a[1]), "r"(a[2]), "r"(a[3]), "r"(b0), "r"(b1));
}
__device__ __forceinline__ void bf16_split2(float a, float b,
                                            uint32_t& hi, uint32_t& lo) {
    __nv_bfloat16 ah = __float2bfloat16(a);
    __nv_bfloat16 bh = __float2bfloat16(b);
    __nv_bfloat16 al = __float2bfloat16(a - __bfloat162float(ah));
    __nv_bfloat16 bl = __float2bfloat16(b - __bfloat162float(bh));
    hi = (uint32_t)*(uint16_t*)&ah | ((uint32_t)*(uint16_t*)&bh << 16);
    lo = (uint32_t)*(uint16_t*)&al | ((uint32_t)*(uint16_t*)&bl << 16);
}
__device__ __forceinline__ void cp16(uint32_t dst, const void* src) {
    asm volatile("cp.async.cg.shared.global [%0], [%1], 16;"
        :: "r"(dst), "l"(src));
}
#define CP_COMMIT() asm volatile("cp.async.commit_group;" ::: "memory")
#define CP_WAIT(n)  asm volatile("cp.async.wait_group %0;" :: "n"(n) : "memory")

// ===========================================================================
// split_inputs: x and Wq/Wk/Wv fp32 -> packed bf16x2 hi/lo planes. BW-bound.
// ===========================================================================
__global__ void __launch_bounds__(256) split_inputs(
        const float* __restrict__ x,  const float* __restrict__ Wq,
        const float* __restrict__ Wk, const float* __restrict__ Wv)
{
    const int NX = MTOT * DW;            // 2621440
    const int NTOT = NX + 3 * WN;        // + 614400
    for (int i = blockIdx.x * 256 + threadIdx.x; i < NTOT;
         i += gridDim.x * 256) {
        if (i < NX) {
            float2 v = ((const float2*)x)[i];
            bf16_split2(v.x, v.y, g_Xh[i], g_Xl[i]);
        } else {
            int j = i - NX;
            int w = j / WN, r = j - w * WN;
            const float2* src = (const float2*)(w == 0 ? Wq : w == 1 ? Wk : Wv);
            float2 v = src[r];
            bf16_split2(v.x, v.y, g_Wh[j], g_Wl[j]);
        }
    }
}

// ===========================================================================
// Projection: double-buffered cp.async GEMM on pre-split bf16 planes.
// CTA tile M=128 x N=64, BK=64, 8 warps (4m x 2n), 2 smem stages.
// ===========================================================================
#define PS_AHI 0
#define PS_ALO 18432
#define PS_BHI 36864
#define PS_BLO 46080
#define PJ_STAGE 55296
#define PJ_SMEM  (2 * PJ_STAGE)   // 110592

__global__ void __launch_bounds__(256, 2) proj_tc_kernel()
{
    const int z = blockIdx.z;
    uint32_t* outh = (z == 0) ? g_Qh : (z == 1) ? g_Kh : g_Vh;
    uint32_t* outl = (z == 0) ? g_Ql : (z == 1) ? g_Kl : g_Vl;
    const uint32_t* wh = g_Wh + z * WN;
    const uint32_t* wl = g_Wl + z * WN;

    extern __shared__ char smem[];
    const uint32_t sb = smem_u32(smem);

    const int tid  = threadIdx.x;
    const int lane = tid & 31;
    const int wid  = tid >> 5;
    const int wm   = (wid & 3) * 32;
    const int wn   = (wid >> 2) * 32;
    const int row0 = blockIdx.y * 128;
    const int col0 = blockIdx.x * 64;
    const int colw = col0 >> 1;

    // loader: chunk c into stage s (no commit inside)
    auto load_chunk = [&](int s, int c) {
        const uint32_t base = sb + s * PJ_STAGE;
        const int kw = c * 32;          // k0/2 in u32
        #pragma unroll
        for (int i = 0; i < 8; i++) {   // A: 2 planes x 128 rows x 8 segs
            const int plane = i >> 2;
            int rem = (tid + i * 256) & 1023;
            int r = rem >> 3, seg = rem & 7;
            const uint32_t* src = (plane ? g_Xl : g_Xh)
                                  + (size_t)(row0 + r) * DW + kw + seg * 4;
            cp16(base + (plane ? PS_ALO : PS_AHI) + r * 144 + seg * 16, src);
        }
        #pragma unroll
        for (int i = 0; i < 4; i++) {   // B: 2 planes x 64 rows x 8 segs
            const int plane = i >> 1;
            int rem = (tid + i * 256) & 511;
            int kk = rem >> 3, seg = rem & 7;
            const uint32_t* src = (plane ? wl : wh)
                                  + (size_t)(c * 64 + kk) * 320 + colw + seg * 4;
            cp16(base + (plane ? PS_BLO : PS_BHI) + kk * 144 + seg * 16, src);
        }
        CP_COMMIT();
    };

    float acc[2][4][4] = {};

    load_chunk(0, 0);

    for (int c = 0; c < 10; c++) {
        if (c < 9) { load_chunk((c + 1) & 1, c + 1); CP_WAIT(1); }
        else       { CP_WAIT(0); }
        __syncthreads();

        const uint32_t base = sb + (c & 1) * PJ_STAGE;
        #pragma unroll
        for (int ks = 0; ks < 4; ks++) {
            const int k = ks * 16;
            uint32_t ah[2][4], al[2][4];
            #pragma unroll
            for (int mi = 0; mi < 2; mi++) {
                uint32_t off = (uint32_t)((wm + mi * 16 + (lane & 15)) * 72
                                          + k + (lane >> 4) * 8) * 2;
                ldsm_x4(ah[mi], base + PS_AHI + off);
                ldsm_x4(al[mi], base + PS_ALO + off);
            }
            uint32_t bh[2][4], bl[2][4];
            #pragma unroll
            for (int nj = 0; nj < 2; nj++) {
                uint32_t off = (uint32_t)((k + (lane & 15)) * 72
                                          + wn + nj * 16 + (lane >> 4) * 8) * 2;
                ldsm_x4_t(bh[nj], base + PS_BHI + off);
                ldsm_x4_t(bl[nj], base + PS_BLO + off);
            }
            #pragma unroll
            for (int mi = 0; mi < 2; mi++)
                #pragma unroll
                for (int ni = 0; ni < 4; ni++) {
                    int nj = ni >> 1, hf = (ni & 1) * 2;
                    mma16816(acc[mi][ni], ah[mi], bh[nj][hf], bh[nj][hf + 1]);
                    mma16816(acc[mi][ni], ah[mi], bl[nj][hf], bl[nj][hf + 1]);
                    mma16816(acc[mi][ni], al[mi], bh[nj][hf], bh[nj][hf + 1]);
                }
        }
        __syncthreads();
    }

    // epilogue: split to bf16 hi/lo planes
    const int gid = lane >> 2, t2 = lane & 3;
    #pragma unroll
    for (int mi = 0; mi < 2; mi++) {
        #pragma unroll
        for (int ni = 0; ni < 4; ni++) {
            int r0r = row0 + wm + mi * 16 + gid;
            int cc  = col0 + wn + ni * 8 + t2 * 2;
            uint32_t h0, l0, h1, l1;
            bf16_split2(acc[mi][ni][0], acc[mi][ni][1], h0, l0);
            bf16_split2(acc[mi][ni][2], acc[mi][ni][3], h1, l1);
            size_t i0 = (size_t)r0r * DW + (cc >> 1);
            size_t i1 = (size_t)(r0r + 8) * DW + (cc >> 1);
            outh[i0] = h0; outl[i0] = l0;
            outh[i1] = h1; outl[i1] = l1;
        }
    }
}

// ===========================================================================
// Tensor-core flash attention.  CTA = (64-q-tile, head, batch), 4 warps.
// ===========================================================================
#define TS 72
#define TILE_B (64 * TS * 2)        // 9216
#define AT_QHI 0
#define AT_QLO (1 * TILE_B)
#define AT_KHI (2 * TILE_B)
#define AT_KLO (3 * TILE_B)
#define AT_VHI (4 * TILE_B)
#define AT_VLO (5 * TILE_B)
#define AT_KM  (6 * TILE_B)
#define AT_QM  (6 * TILE_B + 256)
#define ATTN2_SMEM (6 * TILE_B + 512)   // 55808

__global__ void __launch_bounds__(128, 4) attn_tc_kernel(
        const int* __restrict__ mask, float* __restrict__ out)
{
    const int q0 = blockIdx.x * 64;
    const int qt = blockIdx.x;
    const int hb = blockIdx.y;
    const int b  = hb & 7;
    const int h  = hb >> 3;

    extern __shared__ char sm[];
    const uint32_t sb = smem_u32(sm);
    float* km_sh = (float*)(sm + AT_KM);
    float* qm_sh = (float*)(sm + AT_QM);

    const int tid  = threadIdx.x;
    const int lane = tid & 31;
    const int w    = tid >> 5;

    // ---- Q tile: 2 planes x 64 rows x 8 segs, plane compile-time
    {
        const uint32_t* qh = g_Qh + (size_t)(b * T_ + q0) * DW + h * 32;
        const uint32_t* ql = g_Ql + (size_t)(b * T_ + q0) * DW + h * 32;
        #pragma unroll
        for (int i = 0; i < 8; i++) {
            const int plane = i >> 2;
            int rem = (tid + i * 128) & 511;
            int r = rem >> 3, seg = rem & 7;
            cp16(sb + (plane ? AT_QLO : AT_QHI) + r * 144 + seg * 16,
                 (plane ? ql : qh) + (size_t)r * DW + seg * 4);
        }
        CP_COMMIT(); CP_WAIT(0);
    }
    __syncthreads();
    if (tid < 64) {
        const uint32_t* ph = (const uint32_t*)(sm + AT_QHI + tid * TS * 2);
        const uint32_t* pl = (const uint32_t*)(sm + AT_QLO + tid * TS * 2);
        uint32_t o = 0;
        #pragma unroll 8
        for (int c = 0; c < 32; c++) o |= (ph[c] | pl[c]) & 0x7FFF7FFFu;
        qm_sh[tid] = o ? 1.0f : 0.0f;
    }

    float m0 = -INFINITY, m1 = -INFINITY, l0 = 0.0f, l1 = 0.0f;
    float O[8][4] = {};

    const int nkt = (q0 == 0) ? (T_ / 64) : (qt + 1);

    for (int kt = 0; kt < nkt; kt++) {
        const int k0 = kt * 64;
        const bool fullmask = kt > qt;
        const bool diag = (kt == qt);

        __syncthreads();

        // ---- K/V tiles: 4 planes x 64 rows x 8 segs, plane compile-time
        {
            const size_t base = (size_t)(b * T_ + k0) * DW + h * 32;
            const uint32_t* kh = g_Kh + base;
            const uint32_t* kl = g_Kl + base;
            const uint32_t* vh = g_Vh + base;
            const uint32_t* vl = g_Vl + base;
            #pragma unroll
            for (int i = 0; i < 16; i++) {
                const int plane = i >> 2;
                const uint32_t dofs = (plane == 0) ? AT_KHI : (plane == 1) ? AT_KLO
                                    : (plane == 2) ? AT_VHI : AT_VLO;
                const uint32_t* src = (plane == 0) ? kh : (plane == 1) ? kl
                                    : (plane == 2) ? vh : vl;
                int rem = (tid + i * 128) & 511;
                int r = rem >> 3, seg = rem & 7;
                cp16(sb + dofs + r * 144 + seg * 16,
                     src + (size_t)r * DW + seg * 4);
            }
            CP_COMMIT(); CP_WAIT(0);
        }
        __syncthreads();

        // ---- key padding mask
        int rowok = 1;
        if (tid < 64) {
            const uint32_t* ph = (const uint32_t*)(sm + AT_KHI + tid * TS * 2);
            const uint32_t* pl = (const uint32_t*)(sm + AT_KLO + tid * TS * 2);
            uint32_t o = 0;
            #pragma unroll 8
            for (int c = 0; c < 32; c++) o |= (ph[c] | pl[c]) & 0x7FFF7FFFu;
            km_sh[tid] = o ? 1.0f : 0.0f;
            rowok = o ? 1 : 0;
        }
        const int allkm = __syncthreads_and(rowok);

        // ---- S = Q K^T (3-term bf16 split)
        float s[8][4] = {};
        #pragma unroll
        for (int ks = 0; ks < 4; ks++) {
            uint32_t ah[4], al[4];
            uint32_t aoff = (uint32_t)((16 * w + (lane & 15)) * TS
                                       + ks * 16 + (lane >> 4) * 8) * 2;
            ldsm_x4(ah, sb + AT_QHI + aoff);
            ldsm_x4(al, sb + AT_QLO + aoff);
            #pragma unroll
            for (int kg = 0; kg < 4; kg++) {
                uint32_t bh[4], bl[4];
                uint32_t boff = (uint32_t)((kg * 16 + (lane & 15)) * TS
                                           + ks * 16 + (lane >> 4) * 8) * 2;
                ldsm_x4(bh, sb + AT_KHI + boff);
                ldsm_x4(bl, sb + AT_KLO + boff);
                mma16816(s[2 * kg],     ah, bh[0], bh[2]);
                mma16816(s[2 * kg],     ah, bl[0], bl[2]);
                mma16816(s[2 * kg],     al, bh[0], bh[2]);
                mma16816(s[2 * kg + 1], ah, bh[1], bh[3]);
                mma16816(s[2 * kg + 1], ah, bl[1], bl[3]);
                mma16816(s[2 * kg + 1], al, bh[1], bh[3]);
            }
        }

        // ---- masks
        const int rbase = q0 + 16 * w + (lane >> 2);
        const int cq = 2 * (lane & 3);
        #pragma unroll
        for (int j = 0; j < 8; j++) {
            #pragma unroll
            for (int e = 0; e < 4; e++) {
                int row = rbase + ((e >> 1) << 3);
                int col = k0 + 8 * j + cq + (e & 1);
                float v = s[j][e] * 0.125f;
                if (!allkm && km_sh[8 * j + cq + (e & 1)] == 0.0f) v = NEG_BIG;
                if (fullmask) v += -10000.0f;
                else if (diag && row <= col) v += -10000.0f;
                s[j][e] = v;
            }
        }

        // ---- online softmax
        float tmax0 = -INFINITY, tmax1 = -INFINITY;
        #pragma unroll
        for (int j = 0; j < 8; j++) {
            tmax0 = fmaxf(tmax0, fmaxf(s[j][0], s[j][1]));
            tmax1 = fmaxf(tmax1, fmaxf(s[j][2], s[j][3]));
        }
        tmax0 = fmaxf(tmax0, __shfl_xor_sync(0xffffffffu, tmax0, 1));
        tmax0 = fmaxf(tmax0, __shfl_xor_sync(0xffffffffu, tmax0, 2));
        tmax1 = fmaxf(tmax1, __shfl_xor_sync(0xffffffffu, tmax1, 1));
        tmax1 = fmaxf(tmax1, __shfl_xor_sync(0xffffffffu, tmax1, 2));

        float mn0 = fmaxf(m0, tmax0), mn1 = fmaxf(m1, tmax1);
        float a0 = __expf(m0 - mn0), a1 = __expf(m1 - mn1);
        m0 = mn0; m1 = mn1;

        float rs0 = 0.0f, rs1 = 0.0f;
        #pragma unroll
        for (int j = 0; j < 8; j++) {
            float p0 = __expf(s[j][0] - m0);
            float p1 = __expf(s[j][1] - m0);
            float p2 = __expf(s[j][2] - m1);
            float p3 = __expf(s[j][3] - m1);
            s[j][0] = p0; s[j][1] = p1; s[j][2] = p2; s[j][3] = p3;
            rs0 += p0 + p1; rs1 += p2 + p3;
        }
        rs0 += __shfl_xor_sync(0xffffffffu, rs0, 1);
        rs0 += __shfl_xor_sync(0xffffffffu, rs0, 2);
        rs1 += __shfl_xor_sync(0xffffffffu, rs1, 1);
        rs1 += __shfl_xor_sync(0xffffffffu, rs1, 2);
        l0 = l0 * a0 + rs0;
        l1 = l1 * a1 + rs1;

        #pragma unroll
        for (int j = 0; j < 8; j++) {
            O[j][0] *= a0; O[j][1] *= a0;
            O[j][2] *= a1; O[j][3] *= a1;
        }

        // ---- O += P @ V
        #pragma unroll
        for (int ks = 0; ks < 4; ks++) {
            uint32_t pah[4], pal[4];
            bf16_split2(s[2 * ks][0],     s[2 * ks][1],     pah[0], pal[0]);
            bf16_split2(s[2 * ks][2],     s[2 * ks][3],     pah[1], pal[1]);
            bf16_split2(s[2 * ks + 1][0], s[2 * ks + 1][1], pah[2], pal[2]);
            bf16_split2(s[2 * ks + 1][2], s[2 * ks + 1][3], pah[3], pal[3]);
            #pragma unroll
            for (int dg = 0; dg < 4; dg++) {
                uint32_t vh[4], vl[4];
                uint32_t voff = (uint32_t)((ks * 16 + (lane & 15)) * TS
                                           + dg * 16 + (lane >> 4) * 8) * 2;
                ldsm_x4_t(vh, sb + AT_VHI + voff);
                ldsm_x4_t(vl, sb + AT_VLO + voff);
                mma16816(O[2 * dg],     pah, vh[0], vh[1]);
                mma16816(O[2 * dg],     pah, vl[0], vl[1]);
                mma16816(O[2 * dg],     pal, vh[0], vh[1]);
                mma16816(O[2 * dg + 1], pah, vh[2], vh[3]);
                mma16816(O[2 * dg + 1], pah, vl[2], vl[3]);
                mma16816(O[2 * dg + 1], pal, vh[2], vh[3]);
            }
        }
    }

    // ---- epilogue
    const int row0g = q0 + 16 * w + (lane >> 2);
    const int row1g = row0g + 8;
    const float f0 = (1.0f / l0) * qm_sh[row0g - q0] * (float)mask[b * T_ + row0g];
    const float f1 = (1.0f / l1) * qm_sh[row1g - q0] * (float)mask[b * T_ + row1g];
    #pragma unroll
    for (int j = 0; j < 8; j++) {
        int col = h * HD + 8 * j + 2 * (lane & 3);
        *(float2*)(out + (size_t)(b * T_ + row0g) * D_ + col) =
            make_float2(O[j][0] * f0, O[j][1] * f0);
        *(float2*)(out + (size_t)(b * T_ + row1g) * D_ + col) =
            make_float2(O[j][2] * f1, O[j][3] * f1);
    }
}

// ---------------------------------------------------------------------------
extern "C" void kernel_launch(void* const* d_in, const int* in_sizes, int n_in,
                              void* d_out, int out_size)
{
    const float* x    = (const float*)d_in[0];
    const int*   mask = (const int*)d_in[1];
    const float* Wq   = (const float*)d_in[2];
    const float* Wk   = (const float*)d_in[3];
    const float* Wv   = (const float*)d_in[4];
    float* out = (float*)d_out;

    cudaFuncSetAttribute(proj_tc_kernel,
                         cudaFuncAttributeMaxDynamicSharedMemorySize, PJ_SMEM);
    cudaFuncSetAttribute(attn_tc_kernel,
                         cudaFuncAttributeMaxDynamicSharedMemorySize, ATTN2_SMEM);

    split_inputs<<<1280, 256>>>(x, Wq, Wk, Wv);

    dim3 gproj(D_ / 64, MTOT / 128, 3);
    proj_tc_kernel<<<gproj, 256, PJ_SMEM>>>();

    dim3 gattn(T_ / 64, H_ * B_);
    attn_tc_kernel<<<gattn, 128, ATTN2_SMEM>>>(mask, out);
}